// round 3
// baseline (speedup 1.0000x reference)
#include <cuda_runtime.h>
#include <math.h>

#define Nn 2000
#define Cc 256
#define Hh 8
#define Dd 32
#define LD 2048
#define N3C 768

typedef unsigned long long u64;

__device__ __forceinline__ u64 pack2(float lo, float hi) {
    u64 r; asm("mov.b64 %0, {%1, %2};" : "=l"(r) : "f"(lo), "f"(hi)); return r;
}
__device__ __forceinline__ void unpack2(u64 v, float& lo, float& hi) {
    asm("mov.b64 {%0, %1}, %2;" : "=f"(lo), "=f"(hi) : "l"(v));
}
__device__ __forceinline__ void ffma2(u64& d, u64 a, u64 b) {
    asm("fma.rn.f32x2 %0, %1, %2, %0;" : "+l"(d) : "l"(a), "l"(b));
}

// ---------------- scratch (static __device__, no allocation) ----------------
__device__ float g_qkv[2][Nn * N3C];      // raw qkv for cls/reg
__device__ float g_q[2][Hh * Nn * Dd];    // normalized q (cls,reg), layout [h][n][d]
__device__ float g_k[2][Hh * Nn * Dd];    // normalized k (cls,reg)
__device__ float g_vn[Hh * Nn * Dd];      // normalized v_cls
__device__ float g_v[Hh * Nn * Dd];       // raw v_cls
__device__ float g_e1[Nn * LD];           // exp(cls logits) current head
__device__ float g_e2[Nn * LD];           // exp(reg logits) current head
__device__ float g_attn[Nn * LD];         // sum over heads of masked attn
__device__ float g_raw[Nn * LD];          // sum over heads of v_norm @ v_norm^T
__device__ float g_S[2][Hh * Nn];         // softmax row sums per head (cls,reg)

// ---------------- zero row sums ----------------
__global__ void k_zeroS() {
    int i = blockIdx.x * 256 + threadIdx.x;
    if (i < Hh * Nn) { g_S[0][i] = 0.f; g_S[1][i] = 0.f; }
}

// ---------------- QKV GEMM: [2000,256] @ [256,768], z=0 cls, z=1 reg --------
__global__ __launch_bounds__(256) void k_gemm(const float* __restrict__ xc,
                                              const float* __restrict__ wc,
                                              const float* __restrict__ xr,
                                              const float* __restrict__ wr) {
    __shared__ float sa[32][258];   // k-major, DUPLICATED: sa[k][2r]=sa[k][2r+1]=a[r][k]
    __shared__ float sb[32][132];   // k-major B tile (natural layout)
    int z = blockIdx.z;
    const float* A = z ? xr : xc;
    const float* B = z ? wr : wc;
    float* Cout = g_qkv[z];
    int t = threadIdx.x, ty = t >> 4, tx = t & 15;
    int r0 = blockIdx.y * 128, c0 = blockIdx.x * 128;
    u64 acc2[8][4];
#pragma unroll
    for (int i = 0; i < 8; i++)
#pragma unroll
        for (int j = 0; j < 4; j++) acc2[i][j] = 0ull;

    for (int kk0 = 0; kk0 < Cc; kk0 += 32) {
        __syncthreads();
        // A: 128 rows x 32 k -> transposed, duplicated store
#pragma unroll
        for (int i = 0; i < 4; i++) {
            int idx = t + i * 256;              // 0..1023
            int rr = idx >> 3, d4 = (idx & 7) * 4;
            float4 av = make_float4(0.f, 0.f, 0.f, 0.f);
            if (r0 + rr < Nn) av = *reinterpret_cast<const float4*>(&A[(r0 + rr) * Cc + kk0 + d4]);
            *reinterpret_cast<u64*>(&sa[d4 + 0][2 * rr]) = pack2(av.x, av.x);
            *reinterpret_cast<u64*>(&sa[d4 + 1][2 * rr]) = pack2(av.y, av.y);
            *reinterpret_cast<u64*>(&sa[d4 + 2][2 * rr]) = pack2(av.z, av.z);
            *reinterpret_cast<u64*>(&sa[d4 + 3][2 * rr]) = pack2(av.w, av.w);
        }
        // B: 32 k x 128 cols -> direct vector store
#pragma unroll
        for (int i = 0; i < 4; i++) {
            int idx = t + i * 256;
            int rr = idx >> 5, c4 = (idx & 31) * 4;
            float4 bv = *reinterpret_cast<const float4*>(&B[(kk0 + rr) * N3C + c0 + c4]);
            *reinterpret_cast<float4*>(&sb[rr][c4]) = bv;
        }
        __syncthreads();
#pragma unroll
        for (int kk = 0; kk < 32; kk++) {
            u64 ad[8];
#pragma unroll
            for (int i = 0; i < 8; i++)
                ad[i] = *reinterpret_cast<const u64*>(&sa[kk][2 * (ty * 8 + i)]);
            ulonglong2 b0 = *reinterpret_cast<const ulonglong2*>(&sb[kk][tx * 8]);
            ulonglong2 b1 = *reinterpret_cast<const ulonglong2*>(&sb[kk][tx * 8 + 4]);
            u64 bb[4] = {b0.x, b0.y, b1.x, b1.y};
#pragma unroll
            for (int i = 0; i < 8; i++)
#pragma unroll
                for (int j = 0; j < 4; j++) ffma2(acc2[i][j], ad[i], bb[j]);
        }
    }
#pragma unroll
    for (int i = 0; i < 8; i++) {
        int gr = r0 + ty * 8 + i;
        if (gr < Nn) {
            float o[8];
#pragma unroll
            for (int j = 0; j < 4; j++) unpack2(acc2[i][j], o[2 * j], o[2 * j + 1]);
            float* dst = &Cout[gr * N3C + c0 + tx * 8];
            *reinterpret_cast<float4*>(dst) = make_float4(o[0], o[1], o[2], o[3]);
            *reinterpret_cast<float4*>(dst + 4) = make_float4(o[4], o[5], o[6], o[7]);
        }
    }
}

// ---------------- normalize + split heads, emit x_ori + zero x region ------
__device__ __forceinline__ float rnorm_of(float x) {
    float s = x * x;
#pragma unroll
    for (int off = 16; off; off >>= 1) s += __shfl_xor_sync(0xffffffffu, s, off);
    return 1.f / (sqrtf(s) + 1e-8f);
}

__global__ __launch_bounds__(256) void k_norm(float* __restrict__ out) {
    int n = blockIdx.x;
    int h = threadIdx.x >> 5;
    int d = threadIdx.x & 31;
    const float* qc_row = g_qkv[0] + n * N3C;
    const float* qr_row = g_qkv[1] + n * N3C;
    float qc = qc_row[h * Dd + d];
    float kc = qc_row[Cc + h * Dd + d];
    float vc = qc_row[2 * Cc + h * Dd + d];
    float qr = qr_row[h * Dd + d];
    float kr = qr_row[Cc + h * Dd + d];

    int idx = (h * Nn + n) * Dd + d;
    g_q[0][idx] = qc * rnorm_of(qc);
    g_k[0][idx] = kc * rnorm_of(kc);
    g_q[1][idx] = qr * rnorm_of(qr);
    g_k[1][idx] = kr * rnorm_of(kr);
    g_vn[idx]   = vc * rnorm_of(vc);
    g_v[idx]    = vc;

    out[n * 2 * Cc + h * Dd + d] = 0.f;         // x region zeroed (atomics target)
    out[n * 2 * Cc + Cc + h * Dd + d] = vc;     // x_ori
}

// ---------------- per-head: 3 GEMMs (cls, reg, raw) + exp + row sums -------
__global__ __launch_bounds__(256) void k_logits(int h) {
    __shared__ float sa[32][258];   // duplicated a
    __shared__ float sb[32][132];
    int t = threadIdx.x, ty = t >> 4, tx = t & 15;
    int r0 = blockIdx.y * 128, c0 = blockIdx.x * 128;
    bool full_c = (c0 + 128 <= Nn);

    for (int p = 0; p < 3; p++) {
        const float* A = (p == 0) ? g_q[0] : (p == 1) ? g_q[1] : g_vn;
        const float* B = (p == 0) ? g_k[0] : (p == 1) ? g_k[1] : g_vn;
        A += h * Nn * Dd;
        B += h * Nn * Dd;
        __syncthreads();
#pragma unroll
        for (int i = 0; i < 4; i++) {
            int idx = t + i * 256;
            int rr = idx >> 3, d4 = (idx & 7) * 4;
            float4 av = make_float4(0.f, 0.f, 0.f, 0.f);
            float4 bv = make_float4(0.f, 0.f, 0.f, 0.f);
            if (r0 + rr < Nn) av = *reinterpret_cast<const float4*>(&A[(r0 + rr) * Dd + d4]);
            if (c0 + rr < Nn) bv = *reinterpret_cast<const float4*>(&B[(c0 + rr) * Dd + d4]);
            *reinterpret_cast<u64*>(&sa[d4 + 0][2 * rr]) = pack2(av.x, av.x);
            *reinterpret_cast<u64*>(&sa[d4 + 1][2 * rr]) = pack2(av.y, av.y);
            *reinterpret_cast<u64*>(&sa[d4 + 2][2 * rr]) = pack2(av.z, av.z);
            *reinterpret_cast<u64*>(&sa[d4 + 3][2 * rr]) = pack2(av.w, av.w);
            sb[d4 + 0][rr] = bv.x; sb[d4 + 1][rr] = bv.y;
            sb[d4 + 2][rr] = bv.z; sb[d4 + 3][rr] = bv.w;
        }
        __syncthreads();
        u64 acc2[8][4];
#pragma unroll
        for (int i = 0; i < 8; i++)
#pragma unroll
            for (int j = 0; j < 4; j++) acc2[i][j] = 0ull;
#pragma unroll
        for (int kk = 0; kk < 32; kk++) {
            u64 ad[8];
#pragma unroll
            for (int i = 0; i < 8; i++)
                ad[i] = *reinterpret_cast<const u64*>(&sa[kk][2 * (ty * 8 + i)]);
            ulonglong2 b0 = *reinterpret_cast<const ulonglong2*>(&sb[kk][tx * 8]);
            ulonglong2 b1 = *reinterpret_cast<const ulonglong2*>(&sb[kk][tx * 8 + 4]);
            u64 bb[4] = {b0.x, b0.y, b1.x, b1.y};
#pragma unroll
            for (int i = 0; i < 8; i++)
#pragma unroll
                for (int j = 0; j < 4; j++) ffma2(acc2[i][j], ad[i], bb[j]);
        }

        if (p < 2) {
            float* E = p ? g_e2 : g_e1;
            float* S = g_S[p] + h * Nn;
#pragma unroll
            for (int i = 0; i < 8; i++) {
                int r = r0 + ty * 8 + i;
                float a[8], e[8];
#pragma unroll
                for (int j = 0; j < 4; j++) unpack2(acc2[i][j], a[2 * j], a[2 * j + 1]);
                float rs = 0.f;
#pragma unroll
                for (int j = 0; j < 8; j++) {
                    int c = c0 + tx * 8 + j;
                    float ev = __expf(25.f * a[j] - 25.f);
                    if (c >= Nn) ev = 0.f;
                    e[j] = ev;
                    rs += ev;
                }
#pragma unroll
                for (int off = 1; off < 16; off <<= 1)
                    rs += __shfl_xor_sync(0xffffffffu, rs, off);
                if (tx == 0 && r < Nn) atomicAdd(&S[r], rs);
                if (r < Nn) {
                    float* dst = &E[r * LD + c0 + tx * 8];
                    if (full_c) {
                        *reinterpret_cast<float4*>(dst) = make_float4(e[0], e[1], e[2], e[3]);
                        *reinterpret_cast<float4*>(dst + 4) = make_float4(e[4], e[5], e[6], e[7]);
                    } else {
#pragma unroll
                        for (int j = 0; j < 8; j++)
                            if (c0 + tx * 8 + j < Nn) dst[j] = e[j];
                    }
                }
            }
        } else {
#pragma unroll
            for (int i = 0; i < 8; i++) {
                int r = r0 + ty * 8 + i;
                if (r >= Nn) continue;
                float a[8];
#pragma unroll
                for (int j = 0; j < 4; j++) unpack2(acc2[i][j], a[2 * j], a[2 * j + 1]);
                float* dst = &g_raw[r * LD + c0 + tx * 8];
                if (full_c) {
                    float4 o0 = make_float4(a[0], a[1], a[2], a[3]);
                    float4 o1 = make_float4(a[4], a[5], a[6], a[7]);
                    if (h) {
                        float4 p0 = *reinterpret_cast<const float4*>(dst);
                        float4 p1 = *reinterpret_cast<const float4*>(dst + 4);
                        o0.x += p0.x; o0.y += p0.y; o0.z += p0.z; o0.w += p0.w;
                        o1.x += p1.x; o1.y += p1.y; o1.z += p1.z; o1.w += p1.w;
                    }
                    *reinterpret_cast<float4*>(dst) = o0;
                    *reinterpret_cast<float4*>(dst + 4) = o1;
                } else {
#pragma unroll
                    for (int j = 0; j < 8; j++) {
                        int c = c0 + tx * 8 + j;
                        if (c < Nn) dst[j] = h ? (dst[j] + a[j]) : a[j];
                    }
                }
            }
        }
    }
}

// ---------------- per-head: weights + mask + attn_sum + x = w @ v ----------
// tile: 128 rows x 128 m-window (2 chunks of 64). thread owns 4r x 4d.
__global__ __launch_bounds__(256) void k_wx(int h, float* __restrict__ out) {
    __shared__ float invS1[128], invS2[128];
    __shared__ float w_sm[64 * 128];   // [m][r], XOR-swizzled
    __shared__ float v_sm[64][32];
    int t = threadIdx.x;
    int r0 = blockIdx.y * 128;
    int mwin = blockIdx.x * 128;

    if (t < 128) {
        int r = r0 + t;
        invS1[t] = (r < Nn) ? 1.f / g_S[0][h * Nn + r] : 0.f;
    } else {
        int r = r0 + t - 128;
        invS2[t - 128] = (r < Nn) ? 1.f / g_S[1][h * Nn + r] : 0.f;
    }
    int rq = t & 31, dq = t >> 5;
    int rq4 = rq * 4;
    u64 acc2[4][2];
#pragma unroll
    for (int r = 0; r < 4; r++) { acc2[r][0] = 0ull; acc2[r][1] = 0ull; }

    for (int mt = 0; mt < 2; mt++) {
        int m0 = mwin + mt * 64;
        __syncthreads();
        // phase A: compute 128x64 w tile, RMW attn, store transposed-swizzled
#pragma unroll
        for (int i = 0; i < 8; i++) {
            int idx = t + i * 256;            // 0..2047
            int rr = idx >> 4;                // 0..127
            int m4 = (idx & 15) * 4;          // 0..60
            int r = r0 + rr, m = m0 + m4;
            float w[4] = {0.f, 0.f, 0.f, 0.f};
            if (r < Nn && m < Nn) {           // Nn%4==0, m%4==0 -> full float4 in-bounds
                int g = r * LD + m;
                float4 a = *reinterpret_cast<const float4*>(&g_e1[g]);
                float4 b = *reinterpret_cast<const float4*>(&g_e2[g]);
                float is1 = invS1[rr], is2 = invS2[rr];
                int bs = (r / 10) * 10;
                float e1v[4] = {a.x, a.y, a.z, a.w};
                float e2v[4] = {b.x, b.y, b.z, b.w};
#pragma unroll
                for (int q = 0; q < 4; q++) {
                    int mm = m + q;
                    float wv = 0.5f * (e1v[q] * is1 + e2v[q] * is2);
                    if (mm >= bs && mm < bs + 9 && mm != r) wv = 0.f;
                    w[q] = wv;
                }
                float4 o = make_float4(w[0], w[1], w[2], w[3]);
                if (h) {
                    float4 pr = *reinterpret_cast<const float4*>(&g_attn[g]);
                    o.x += pr.x; o.y += pr.y; o.z += pr.z; o.w += pr.w;
                }
                *reinterpret_cast<float4*>(&g_attn[g]) = o;
            }
            int xt = ((m4 >> 2) & 7) * 4;
            int base = m4 * 128 + (rr ^ xt);
            w_sm[base]       = w[0];
            w_sm[base + 128] = w[1];
            w_sm[base + 256] = w[2];
            w_sm[base + 384] = w[3];
        }
        // v tile: 64 x 32
#pragma unroll
        for (int i = 0; i < 2; i++) {
            int idx = t + i * 256;
            int mm = idx >> 3, d4 = (idx & 7) * 4;
            float4 vv = make_float4(0.f, 0.f, 0.f, 0.f);
            if (m0 + mm < Nn) vv = *reinterpret_cast<const float4*>(&g_v[(h * Nn + m0 + mm) * Dd + d4]);
            *reinterpret_cast<float4*>(&v_sm[mm][d4]) = vv;
        }
        __syncthreads();
        // phase B: acc[r][d] += w[m][r] * v[m][d]
#pragma unroll 4
        for (int m = 0; m < 64; m++) {
            int xt = ((m >> 2) & 7) * 4;
            float4 wf = *reinterpret_cast<const float4*>(&w_sm[m * 128 + (rq4 ^ xt)]);
            ulonglong2 v2 = *reinterpret_cast<const ulonglong2*>(&v_sm[m][dq * 4]);
            u64 w0 = pack2(wf.x, wf.x), w1 = pack2(wf.y, wf.y);
            u64 w2 = pack2(wf.z, wf.z), w3 = pack2(wf.w, wf.w);
            ffma2(acc2[0][0], w0, v2.x); ffma2(acc2[0][1], w0, v2.y);
            ffma2(acc2[1][0], w1, v2.x); ffma2(acc2[1][1], w1, v2.y);
            ffma2(acc2[2][0], w2, v2.x); ffma2(acc2[2][1], w2, v2.y);
            ffma2(acc2[3][0], w3, v2.x); ffma2(acc2[3][1], w3, v2.y);
        }
    }
#pragma unroll
    for (int r = 0; r < 4; r++) {
        int gr = r0 + rq4 + r;
        if (gr < Nn) {
            float* dst = &out[gr * 2 * Cc + h * Dd + dq * 4];
            float lo, hi;
            unpack2(acc2[r][0], lo, hi);
            atomicAdd(dst + 0, lo);
            atomicAdd(dst + 1, hi);
            unpack2(acc2[r][1], lo, hi);
            atomicAdd(dst + 2, lo);
            atomicAdd(dst + 3, hi);
        }
    }
}

// ---------------- final similarity softmax + masked renorm -----------------
__global__ __launch_bounds__(256) void k_sim(float* __restrict__ out) {
    __shared__ float e_row[Nn];
    __shared__ float red[2][8];
    int r = blockIdx.x, t = threadIdx.x;
    float se = 0.f, sm = 0.f;
    for (int m4 = t * 4; m4 < Nn; m4 += 1024) {
        float4 a = *reinterpret_cast<const float4*>(&g_attn[r * LD + m4]);
        float4 rw = *reinterpret_cast<const float4*>(&g_raw[r * LD + m4]);
        float e0 = __expf(a.x * 0.125f), e1 = __expf(a.y * 0.125f);
        float e2 = __expf(a.z * 0.125f), e3 = __expf(a.w * 0.125f);
        e_row[m4 + 0] = e0; e_row[m4 + 1] = e1;
        e_row[m4 + 2] = e2; e_row[m4 + 3] = e3;
        se += e0 + e1 + e2 + e3;
        if (rw.x > 6.0f) sm += e0;
        if (rw.y > 6.0f) sm += e1;
        if (rw.z > 6.0f) sm += e2;
        if (rw.w > 6.0f) sm += e3;
    }
#pragma unroll
    for (int off = 16; off; off >>= 1) {
        se += __shfl_xor_sync(0xffffffffu, se, off);
        sm += __shfl_xor_sync(0xffffffffu, sm, off);
    }
    int wid = t >> 5, lane = t & 31;
    if (!lane) { red[0][wid] = se; red[1][wid] = sm; }
    __syncthreads();
    if (t == 0) {
        float a = 0.f, b = 0.f;
        for (int i = 0; i < 8; i++) { a += red[0][i]; b += red[1][i]; }
        red[0][0] = a; red[1][0] = b;
    }
    __syncthreads();
    float S = red[0][0], Sm = red[1][0];
    float invS = 1.f / S;
    float invden = 1.f / (Sm * invS + 1e-8f);
    float* orow = &out[Nn * 2 * Cc + r * Nn];
    for (int m4 = t * 4; m4 < Nn; m4 += 1024) {
        float4 rw = *reinterpret_cast<const float4*>(&g_raw[r * LD + m4]);
        float4 o;
        o.x = (rw.x > 6.0f) ? e_row[m4 + 0] * invS * invden : 0.f;
        o.y = (rw.y > 6.0f) ? e_row[m4 + 1] * invS * invden : 0.f;
        o.z = (rw.z > 6.0f) ? e_row[m4 + 2] * invS * invden : 0.f;
        o.w = (rw.w > 6.0f) ? e_row[m4 + 3] * invS * invden : 0.f;
        *reinterpret_cast<float4*>(&orow[m4]) = o;
    }
}

// ---------------- launch ----------------------------------------------------
extern "C" void kernel_launch(void* const* d_in, const int* in_sizes, int n_in,
                              void* d_out, int out_size) {
    const float* x_cls = (const float*)d_in[0];
    const float* x_reg = (const float*)d_in[1];
    const float* W_cls = (const float*)d_in[2];
    const float* W_reg = (const float*)d_in[3];
    float* out = (float*)d_out;

    k_zeroS<<<(Hh * Nn + 255) / 256, 256>>>();
    k_gemm<<<dim3(6, 16, 2), 256>>>(x_cls, W_cls, x_reg, W_reg);
    k_norm<<<Nn, 256>>>(out);
    for (int h = 0; h < Hh; h++) {
        k_logits<<<dim3(16, 16), 256>>>(h);
        k_wx<<<dim3(16, 16), 256>>>(h, out);
    }
    k_sim<<<Nn, 256>>>(out);
}

// round 6
// speedup vs baseline: 1.9241x; 1.9241x over previous
#include <cuda_runtime.h>
#include <cuda_bf16.h>
#include <math.h>
#include <stdint.h>

#define Nn 2000
#define Cc 256
#define Hh 8
#define Dd 32
#define LD 2048
#define N3C 768

// ---------------- scratch (static __device__, no allocation) ----------------
__device__ float g_qkv[2][Nn * N3C];             // raw qkv for cls/reg
__device__ float g_v[Hh * Nn * Dd];              // raw v_cls [h][n][d]
__device__ __nv_bfloat16 g_qA[2][Hh * Nn * 128]; // q split, A-side dup [hi,lo,hi,lo]
__device__ __nv_bfloat16 g_kB[2][Hh * Nn * 128]; // k split, B-side dup [hi,hi,lo,lo]
__device__ __nv_bfloat16 g_vnP[Nn * 256];        // vn plain bf16, head-concat [n][h*32+d]
__device__ float g_e[2][Hh][Nn * LD];            // exp(logits) per (p, head), fp32
__device__ float g_raw[Nn * LD];                 // sum over heads of vn@vn^T
__device__ float g_S[2][Hh * Nn];                // softmax row sums (fp32)

// ---------------- PTX helpers ----------------
__device__ __forceinline__ uint32_t smem_u32(const void* p) {
    uint32_t r;
    asm("{ .reg .u64 t; cvta.to.shared.u64 t, %1; cvt.u32.u64 %0, t; }" : "=r"(r) : "l"(p));
    return r;
}
#define LDSM4(r, addr) \
    asm volatile("ldmatrix.sync.aligned.m8n8.x4.shared.b16 {%0,%1,%2,%3}, [%4];" \
        : "=r"((r)[0]), "=r"((r)[1]), "=r"((r)[2]), "=r"((r)[3]) : "r"(addr))
#define MMA_BF16(c, a, b0v, b1v) \
    asm volatile("mma.sync.aligned.m16n8k16.row.col.f32.bf16.bf16.f32 " \
        "{%0,%1,%2,%3}, {%4,%5,%6,%7}, {%8,%9}, {%0,%1,%2,%3};" \
        : "+f"((c)[0]), "+f"((c)[1]), "+f"((c)[2]), "+f"((c)[3]) \
        : "r"((a)[0]), "r"((a)[1]), "r"((a)[2]), "r"((a)[3]), "r"(b0v), "r"(b1v))

// ---------------- zero row sums ----------------
__global__ void k_zeroS() {
    int i = blockIdx.x * 256 + threadIdx.x;
    if (i < 2 * Hh * Nn) ((float*)g_S)[i] = 0.f;
}

// ---------------- QKV GEMM: [2000,256] @ [256,768] --------------------------
__global__ __launch_bounds__(256) void k_gemm(const float* __restrict__ xc,
                                              const float* __restrict__ wc,
                                              const float* __restrict__ xr,
                                              const float* __restrict__ wr) {
    __shared__ float sa[32][132];
    __shared__ float sb[32][132];
    int z = blockIdx.z;
    const float* A = z ? xr : xc;
    const float* B = z ? wr : wc;
    float* Cout = g_qkv[z];
    int t = threadIdx.x, ty = t >> 4, tx = t & 15;
    int r0 = blockIdx.y * 128, c0 = blockIdx.x * 128;
    float acc[8][8];
#pragma unroll
    for (int i = 0; i < 8; i++)
#pragma unroll
        for (int j = 0; j < 8; j++) acc[i][j] = 0.f;

    for (int kk0 = 0; kk0 < Cc; kk0 += 32) {
        __syncthreads();
#pragma unroll
        for (int i = 0; i < 4; i++) {
            int idx = t + i * 256;
            int rr = idx >> 3, d4 = (idx & 7) * 4;
            float4 av = make_float4(0.f, 0.f, 0.f, 0.f);
            if (r0 + rr < Nn) av = *reinterpret_cast<const float4*>(&A[(r0 + rr) * Cc + kk0 + d4]);
            sa[d4 + 0][rr] = av.x; sa[d4 + 1][rr] = av.y;
            sa[d4 + 2][rr] = av.z; sa[d4 + 3][rr] = av.w;
        }
#pragma unroll
        for (int i = 0; i < 4; i++) {
            int idx = t + i * 256;
            int rr = idx >> 5, c4 = (idx & 31) * 4;
            float4 bv = *reinterpret_cast<const float4*>(&B[(kk0 + rr) * N3C + c0 + c4]);
            *reinterpret_cast<float4*>(&sb[rr][c4]) = bv;
        }
        __syncthreads();
#pragma unroll
        for (int kk = 0; kk < 32; kk++) {
            float4 a0 = *reinterpret_cast<const float4*>(&sa[kk][ty * 8]);
            float4 a1 = *reinterpret_cast<const float4*>(&sa[kk][ty * 8 + 4]);
            float4 b0 = *reinterpret_cast<const float4*>(&sb[kk][tx * 8]);
            float4 b1 = *reinterpret_cast<const float4*>(&sb[kk][tx * 8 + 4]);
            float a[8] = {a0.x, a0.y, a0.z, a0.w, a1.x, a1.y, a1.z, a1.w};
            float b[8] = {b0.x, b0.y, b0.z, b0.w, b1.x, b1.y, b1.z, b1.w};
#pragma unroll
            for (int i = 0; i < 8; i++)
#pragma unroll
                for (int j = 0; j < 8; j++) acc[i][j] = fmaf(a[i], b[j], acc[i][j]);
        }
    }
#pragma unroll
    for (int i = 0; i < 8; i++) {
        int gr = r0 + ty * 8 + i;
        if (gr < Nn) {
            float* dst = &Cout[gr * N3C + c0 + tx * 8];
            *reinterpret_cast<float4*>(dst) = make_float4(acc[i][0], acc[i][1], acc[i][2], acc[i][3]);
            *reinterpret_cast<float4*>(dst + 4) = make_float4(acc[i][4], acc[i][5], acc[i][6], acc[i][7]);
        }
    }
}

// ---------------- normalize + bf16-split + emit x_ori ----------------------
__device__ __forceinline__ float rnorm_of(float x) {
    float s = x * x;
#pragma unroll
    for (int off = 16; off; off >>= 1) s += __shfl_xor_sync(0xffffffffu, s, off);
    return 1.f / (sqrtf(s) + 1e-8f);
}
__device__ __forceinline__ void split_A(__nv_bfloat16* p, int d, float x) {
    __nv_bfloat16 hi = __float2bfloat16(x);
    __nv_bfloat16 lo = __float2bfloat16(x - __bfloat162float(hi));
    p[d] = hi; p[32 + d] = lo; p[64 + d] = hi; p[96 + d] = lo;
}
__device__ __forceinline__ void split_B(__nv_bfloat16* p, int d, float x) {
    __nv_bfloat16 hi = __float2bfloat16(x);
    __nv_bfloat16 lo = __float2bfloat16(x - __bfloat162float(hi));
    p[d] = hi; p[32 + d] = hi; p[64 + d] = lo; p[96 + d] = lo;
}

__global__ __launch_bounds__(256) void k_norm(float* __restrict__ out) {
    int n = blockIdx.x;
    int h = threadIdx.x >> 5;
    int d = threadIdx.x & 31;
    const float* rc = g_qkv[0] + n * N3C;
    const float* rr = g_qkv[1] + n * N3C;
    float qc = rc[h * Dd + d], kc = rc[Cc + h * Dd + d], vc = rc[2 * Cc + h * Dd + d];
    float qr = rr[h * Dd + d], kr = rr[Cc + h * Dd + d];

    float qcn = qc * rnorm_of(qc), kcn = kc * rnorm_of(kc), vcn = vc * rnorm_of(vc);
    float qrn = qr * rnorm_of(qr), krn = kr * rnorm_of(kr);

    int base = (h * Nn + n) * 128;
    split_A(&g_qA[0][base], d, qcn);
    split_A(&g_qA[1][base], d, qrn);
    split_B(&g_kB[0][base], d, kcn);
    split_B(&g_kB[1][base], d, krn);
    g_vnP[n * 256 + h * Dd + d] = __float2bfloat16(vcn);
    g_v[(h * Nn + n) * Dd + d] = vc;

    out[n * 2 * Cc + h * Dd + d] = 0.f;
    out[n * 2 * Cc + Cc + h * Dd + d] = vc;
}

// ---------------- tensor logits: all heads+p in one launch ------------------
// grid (16 ctiles, 16 rtiles, 16 = h*2+p), 256 threads (8 warps, 2x4)
__global__ __launch_bounds__(256) void k_logits_t() {
    extern __shared__ __nv_bfloat16 smbf[];
    __nv_bfloat16* sA = smbf;                 // [128][136]
    __nv_bfloat16* sB = smbf + 128 * 136;
    int t = threadIdx.x, lane = t & 31, wid = t >> 5;
    int wr = wid >> 2, wc = wid & 3;
    int c0 = blockIdx.x * 128, r0 = blockIdx.y * 128;
    int p = blockIdx.z & 1, h = blockIdx.z >> 1;
    const __nv_bfloat16* A = g_qA[p] + h * Nn * 128;
    const __nv_bfloat16* B = g_kB[p] + h * Nn * 128;

#pragma unroll
    for (int i = 0; i < 8; i++) {
        int idx = t + i * 256;          // 0..2047
        int row = idx >> 4, c8 = (idx & 15) * 8;
        uint4 va = make_uint4(0, 0, 0, 0), vb = make_uint4(0, 0, 0, 0);
        if (r0 + row < Nn) va = *reinterpret_cast<const uint4*>(A + (r0 + row) * 128 + c8);
        if (c0 + row < Nn) vb = *reinterpret_cast<const uint4*>(B + (c0 + row) * 128 + c8);
        *reinterpret_cast<uint4*>(sA + row * 136 + c8) = va;
        *reinterpret_cast<uint4*>(sB + row * 136 + c8) = vb;
    }
    __syncthreads();

    uint32_t a_base = smem_u32(sA) + ((wr * 64 + (lane & 15)) * 136 + (lane >> 4) * 8) * 2;
    int bn = (lane & 7) + (lane >> 4) * 8;
    uint32_t b_base = smem_u32(sB) + ((wc * 32 + bn) * 136 + ((lane >> 3) & 1) * 8) * 2;

    float acc[4][4][4];
#pragma unroll
    for (int i = 0; i < 4; i++)
#pragma unroll
        for (int j = 0; j < 4; j++)
#pragma unroll
            for (int q = 0; q < 4; q++) acc[i][j][q] = 0.f;

#pragma unroll
    for (int ks = 0; ks < 8; ks++) {
        uint32_t a[4][4], b[2][4];
#pragma unroll
        for (int mt = 0; mt < 4; mt++) LDSM4(a[mt], a_base + (mt * 16 * 136 + ks * 16) * 2);
#pragma unroll
        for (int n2 = 0; n2 < 2; n2++) LDSM4(b[n2], b_base + (n2 * 16 * 136 + ks * 16) * 2);
#pragma unroll
        for (int mt = 0; mt < 4; mt++)
#pragma unroll
            for (int nt = 0; nt < 4; nt++)
                MMA_BF16(acc[mt][nt], a[mt], b[nt >> 1][(nt & 1) * 2], b[nt >> 1][(nt & 1) * 2 + 1]);
    }

    float* E = &g_e[p][h][0];
    float* S = &g_S[p][h * Nn];
    int r_base = r0 + wr * 64 + (lane >> 2);
    int c_base = c0 + wc * 32 + (lane & 3) * 2;
#pragma unroll
    for (int mt = 0; mt < 4; mt++) {
        int r_lo = r_base + mt * 16, r_hi = r_lo + 8;
        float rs_lo = 0.f, rs_hi = 0.f;
#pragma unroll
        for (int nt = 0; nt < 4; nt++) {
            int c = c_base + nt * 8;
            bool cok = (c < Nn);
            float e0 = cok ? __expf(25.f * acc[mt][nt][0] - 25.f) : 0.f;
            float e1 = cok ? __expf(25.f * acc[mt][nt][1] - 25.f) : 0.f;
            float e2 = cok ? __expf(25.f * acc[mt][nt][2] - 25.f) : 0.f;
            float e3 = cok ? __expf(25.f * acc[mt][nt][3] - 25.f) : 0.f;
            rs_lo += e0 + e1;
            rs_hi += e2 + e3;
            if (cok && r_lo < Nn) *reinterpret_cast<float2*>(&E[r_lo * LD + c]) = make_float2(e0, e1);
            if (cok && r_hi < Nn) *reinterpret_cast<float2*>(&E[r_hi * LD + c]) = make_float2(e2, e3);
        }
        rs_lo += __shfl_xor_sync(0xffffffffu, rs_lo, 1);
        rs_lo += __shfl_xor_sync(0xffffffffu, rs_lo, 2);
        rs_hi += __shfl_xor_sync(0xffffffffu, rs_hi, 1);
        rs_hi += __shfl_xor_sync(0xffffffffu, rs_hi, 2);
        if ((lane & 3) == 0) {
            if (r_lo < Nn) atomicAdd(&S[r_lo], rs_lo);
            if (r_hi < Nn) atomicAdd(&S[r_hi], rs_hi);
        }
    }
}

// ---------------- tensor raw: sum over heads of vn@vn^T (K=256 bf16) --------
__global__ __launch_bounds__(256) void k_raw_t() {
    extern __shared__ __nv_bfloat16 smbf[];
    __nv_bfloat16* sA = smbf;
    __nv_bfloat16* sB = smbf + 128 * 136;
    int t = threadIdx.x, lane = t & 31, wid = t >> 5;
    int wr = wid >> 2, wc = wid & 3;
    int c0 = blockIdx.x * 128, r0 = blockIdx.y * 128;

    float acc[4][4][4];
#pragma unroll
    for (int i = 0; i < 4; i++)
#pragma unroll
        for (int j = 0; j < 4; j++)
#pragma unroll
            for (int q = 0; q < 4; q++) acc[i][j][q] = 0.f;

    uint32_t a_base = smem_u32(sA) + ((wr * 64 + (lane & 15)) * 136 + (lane >> 4) * 8) * 2;
    int bn = (lane & 7) + (lane >> 4) * 8;
    uint32_t b_base = smem_u32(sB) + ((wc * 32 + bn) * 136 + ((lane >> 3) & 1) * 8) * 2;

    for (int kc = 0; kc < 2; kc++) {
        __syncthreads();
#pragma unroll
        for (int i = 0; i < 8; i++) {
            int idx = t + i * 256;
            int row = idx >> 4, c8 = (idx & 15) * 8;
            uint4 va = make_uint4(0, 0, 0, 0), vb = make_uint4(0, 0, 0, 0);
            if (r0 + row < Nn) va = *reinterpret_cast<const uint4*>(&g_vnP[(r0 + row) * 256 + kc * 128 + c8]);
            if (c0 + row < Nn) vb = *reinterpret_cast<const uint4*>(&g_vnP[(c0 + row) * 256 + kc * 128 + c8]);
            *reinterpret_cast<uint4*>(sA + row * 136 + c8) = va;
            *reinterpret_cast<uint4*>(sB + row * 136 + c8) = vb;
        }
        __syncthreads();
#pragma unroll
        for (int ks = 0; ks < 8; ks++) {
            uint32_t a[4][4], b[2][4];
#pragma unroll
            for (int mt = 0; mt < 4; mt++) LDSM4(a[mt], a_base + (mt * 16 * 136 + ks * 16) * 2);
#pragma unroll
            for (int n2 = 0; n2 < 2; n2++) LDSM4(b[n2], b_base + (n2 * 16 * 136 + ks * 16) * 2);
#pragma unroll
            for (int mt = 0; mt < 4; mt++)
#pragma unroll
                for (int nt = 0; nt < 4; nt++)
                    MMA_BF16(acc[mt][nt], a[mt], b[nt >> 1][(nt & 1) * 2], b[nt >> 1][(nt & 1) * 2 + 1]);
        }
    }

    int r_base = r0 + wr * 64 + (lane >> 2);
    int c_base = c0 + wc * 32 + (lane & 3) * 2;
#pragma unroll
    for (int mt = 0; mt < 4; mt++) {
        int r_lo = r_base + mt * 16, r_hi = r_lo + 8;
#pragma unroll
        for (int nt = 0; nt < 4; nt++) {
            int c = c_base + nt * 8;
            if (c < Nn) {
                if (r_lo < Nn)
                    *reinterpret_cast<float2*>(&g_raw[r_lo * LD + c]) =
                        make_float2(acc[mt][nt][0], acc[mt][nt][1]);
                if (r_hi < Nn)
                    *reinterpret_cast<float2*>(&g_raw[r_hi * LD + c]) =
                        make_float2(acc[mt][nt][2], acc[mt][nt][3]);
            }
        }
    }
}

// ---------------- per-head x = w @ v (z = 8 heads) ---------------------------
__global__ __launch_bounds__(256) void k_wx(float* __restrict__ out) {
    __shared__ float invS1[64], invS2[64];
    __shared__ float w_sm[64][64];
    __shared__ float v_sm[64][32];
    int h = blockIdx.z;
    int t = threadIdx.x;
    int r0 = blockIdx.y * 64;
    int mc = blockIdx.x * 256;
    const float* E1 = &g_e[0][h][0];
    const float* E2 = &g_e[1][h][0];

    if (t < 64) {
        int r = r0 + t;
        invS1[t] = (r < Nn) ? 0.5f / g_S[0][h * Nn + r] : 0.f;
    } else if (t < 128) {
        int r = r0 + t - 64;
        invS2[t - 64] = (r < Nn) ? 0.5f / g_S[1][h * Nn + r] : 0.f;
    }
    int d = t & 31, rg = t >> 5;
    float acc[8];
#pragma unroll
    for (int i = 0; i < 8; i++) acc[i] = 0.f;

    for (int mt = 0; mt < 4; mt++) {
        int m0 = mc + mt * 64;
        __syncthreads();
#pragma unroll
        for (int i = 0; i < 4; i++) {
            int idx = t + i * 256;
            int rr = idx >> 4, m4 = (idx & 15) * 4;
            int r = r0 + rr, m = m0 + m4;
            float w[4] = {0.f, 0.f, 0.f, 0.f};
            if (r < Nn) {
                int g = r * LD + m;
                float4 a = *reinterpret_cast<const float4*>(&E1[g]);
                float4 b = *reinterpret_cast<const float4*>(&E2[g]);
                float e1v[4] = {a.x, a.y, a.z, a.w};
                float e2v[4] = {b.x, b.y, b.z, b.w};
                float is1 = invS1[rr], is2 = invS2[rr];
                int bs = (r / 10) * 10;
#pragma unroll
                for (int q = 0; q < 4; q++) {
                    int mm = m + q;
                    float wv = e1v[q] * is1 + e2v[q] * is2;
                    if (mm >= bs && mm < bs + 9 && mm != r) wv = 0.f;
                    w[q] = wv;
                }
            }
            *reinterpret_cast<float4*>(&w_sm[rr][m4]) = make_float4(w[0], w[1], w[2], w[3]);
        }
#pragma unroll
        for (int i = 0; i < 2; i++) {
            int idx = t + i * 256;
            int mm = idx >> 3, d4 = (idx & 7) * 4;
            float4 vv = make_float4(0.f, 0.f, 0.f, 0.f);
            if (m0 + mm < Nn) vv = *reinterpret_cast<const float4*>(&g_v[(h * Nn + m0 + mm) * Dd + d4]);
            *reinterpret_cast<float4*>(&v_sm[mm][d4]) = vv;
        }
        __syncthreads();
#pragma unroll 4
        for (int m4 = 0; m4 < 16; m4++) {
            float v0 = v_sm[m4 * 4 + 0][d];
            float v1 = v_sm[m4 * 4 + 1][d];
            float v2 = v_sm[m4 * 4 + 2][d];
            float v3 = v_sm[m4 * 4 + 3][d];
#pragma unroll
            for (int i = 0; i < 8; i++) {
                float4 w4 = *reinterpret_cast<const float4*>(&w_sm[rg * 8 + i][m4 * 4]);
                acc[i] = fmaf(w4.x, v0, acc[i]);
                acc[i] = fmaf(w4.y, v1, acc[i]);
                acc[i] = fmaf(w4.z, v2, acc[i]);
                acc[i] = fmaf(w4.w, v3, acc[i]);
            }
        }
    }
#pragma unroll
    for (int i = 0; i < 8; i++) {
        int r = r0 + rg * 8 + i;
        if (r < Nn) atomicAdd(&out[r * 2 * Cc + h * Dd + d], acc[i]);
    }
}

// ---------------- final sim: recompute sum_h w, softmax, mask, renorm -------
__global__ __launch_bounds__(256) void k_sim(float* __restrict__ out) {
    __shared__ float e_row[Nn];
    __shared__ float red[2][8];
    __shared__ float sinv[16];
    int r = blockIdx.x, t = threadIdx.x;
    if (t < 16) {
        int p = t >> 3, hh = t & 7;
        sinv[t] = 0.5f / g_S[p][hh * Nn + r];
    }
    __syncthreads();
    int bs = (r / 10) * 10;
    float se = 0.f, sm = 0.f;
    for (int m4 = t * 4; m4 < Nn; m4 += 1024) {
        float ac[4] = {0.f, 0.f, 0.f, 0.f};
#pragma unroll
        for (int p = 0; p < 2; p++)
#pragma unroll
            for (int hh = 0; hh < 8; hh++) {
                float4 ev = *reinterpret_cast<const float4*>(&g_e[p][hh][r * LD + m4]);
                float is = sinv[p * 8 + hh];
                ac[0] = fmaf(ev.x, is, ac[0]);
                ac[1] = fmaf(ev.y, is, ac[1]);
                ac[2] = fmaf(ev.z, is, ac[2]);
                ac[3] = fmaf(ev.w, is, ac[3]);
            }
#pragma unroll
        for (int q = 0; q < 4; q++) {
            int mm = m4 + q;
            if (mm >= bs && mm < bs + 9 && mm != r) ac[q] = 0.f;
        }
        float4 rw = *reinterpret_cast<const float4*>(&g_raw[r * LD + m4]);
        float e0 = __expf(ac[0] * 0.125f), e1 = __expf(ac[1] * 0.125f);
        float e2 = __expf(ac[2] * 0.125f), e3 = __expf(ac[3] * 0.125f);
        e_row[m4 + 0] = e0; e_row[m4 + 1] = e1;
        e_row[m4 + 2] = e2; e_row[m4 + 3] = e3;
        se += e0 + e1 + e2 + e3;
        if (rw.x > 6.0f) sm += e0;
        if (rw.y > 6.0f) sm += e1;
        if (rw.z > 6.0f) sm += e2;
        if (rw.w > 6.0f) sm += e3;
    }
#pragma unroll
    for (int off = 16; off; off >>= 1) {
        se += __shfl_xor_sync(0xffffffffu, se, off);
        sm += __shfl_xor_sync(0xffffffffu, sm, off);
    }
    int wid = t >> 5, lane = t & 31;
    if (!lane) { red[0][wid] = se; red[1][wid] = sm; }
    __syncthreads();
    if (t == 0) {
        float a = 0.f, b = 0.f;
        for (int i = 0; i < 8; i++) { a += red[0][i]; b += red[1][i]; }
        red[0][0] = a; red[1][0] = b;
    }
    __syncthreads();
    float S = red[0][0], Sm = red[1][0];
    float invS = 1.f / S;
    float invden = 1.f / (Sm * invS + 1e-8f);
    float* orow = &out[Nn * 2 * Cc + r * Nn];
    for (int m4 = t * 4; m4 < Nn; m4 += 1024) {
        float4 rw = *reinterpret_cast<const float4*>(&g_raw[r * LD + m4]);
        float4 o;
        o.x = (rw.x > 6.0f) ? e_row[m4 + 0] * invS * invden : 0.f;
        o.y = (rw.y > 6.0f) ? e_row[m4 + 1] * invS * invden : 0.f;
        o.z = (rw.z > 6.0f) ? e_row[m4 + 2] * invS * invden : 0.f;
        o.w = (rw.w > 6.0f) ? e_row[m4 + 3] * invS * invden : 0.f;
        *reinterpret_cast<float4*>(&orow[m4]) = o;
    }
}

// ---------------- launch ----------------------------------------------------
extern "C" void kernel_launch(void* const* d_in, const int* in_sizes, int n_in,
                              void* d_out, int out_size) {
    const float* x_cls = (const float*)d_in[0];
    const float* x_reg = (const float*)d_in[1];
    const float* W_cls = (const float*)d_in[2];
    const float* W_reg = (const float*)d_in[3];
    float* out = (float*)d_out;

    const int SM_T = 2 * 128 * 136 * 2;   // 69632 B
    cudaFuncSetAttribute(k_logits_t, cudaFuncAttributeMaxDynamicSharedMemorySize, SM_T);
    cudaFuncSetAttribute(k_raw_t, cudaFuncAttributeMaxDynamicSharedMemorySize, SM_T);

    k_zeroS<<<(2 * Hh * Nn + 255) / 256, 256>>>();
    k_gemm<<<dim3(6, 16, 2), 256>>>(x_cls, W_cls, x_reg, W_reg);
    k_norm<<<Nn, 256>>>(out);
    k_logits_t<<<dim3(16, 16, 16), 256, SM_T>>>();
    k_raw_t<<<dim3(16, 16), 256, SM_T>>>();
    k_wx<<<dim3(8, 32, 8), 256>>>(out);
    k_sim<<<Nn, 256>>>(out);
}